// round 15
// baseline (speedup 1.0000x reference)
#include <cuda_runtime.h>

// ---------------- problem constants ----------------
#define HWT    80
#define NVOX   (HWT*HWT*HWT)      // 512000
#define CIN    32
#define DIM    48
#define NHEADS 8
#define HD     6
#define NMOT   (NHEADS*3*NVOX)
#define LN_EPS 1e-5f

typedef unsigned long long ull;

// ---------------- packed fp32x2 helpers (sm_103a) ----------------
#define FMA_F32X2(d, a, b, c) \
    asm("fma.rn.f32x2 %0, %1, %2, %3;" : "=l"(d) : "l"(a), "l"(b), "l"(c))
#define ADD_F32X2(d, a, b) \
    asm("add.rn.f32x2 %0, %1, %2;" : "=l"(d) : "l"(a), "l"(b))
#define PACK_F32X2(out, lo, hi) \
    asm("mov.b64 %0, {%1, %2};" : "=l"(out) : "f"(lo), "f"(hi))
#define UNPACK_F32X2(lo, hi, in) \
    asm("mov.b64 {%0, %1}, %2;" : "=f"(lo), "=f"(hi) : "l"(in))

// ---------------- cp.async helpers ----------------
__device__ __forceinline__ void cp_async16(void* s, const void* g) {
    unsigned saddr = (unsigned)__cvta_generic_to_shared(s);
    asm volatile("cp.async.cg.shared.global [%0], [%1], 16;\n" :: "r"(saddr), "l"(g));
}
#define CP_COMMIT()  asm volatile("cp.async.commit_group;\n" ::: "memory")
#define CP_WAIT(n)   asm volatile("cp.async.wait_group %0;\n" :: "n"(n) : "memory")

// ---------------- scratch (static device globals) ----------------
// q/k pair-interleaved: [24 d-pairs][NVOX][2]
__device__ float g_q[(size_t)DIM*NVOX];
__device__ float g_k[(size_t)DIM*NVOX];
__device__ float g_partial[1600*NHEADS];

// ===== kernel A: Linear(32->48)+LN, 8 vox x 12 d / thread, cp.async =========
#define CS2   8
#define NSL   4
#define PVOX  512
#define PROJ_SMEM ((CIN*DIM + NSL*CS2*PVOX)*4)   // 71680 B

__global__ __launch_bounds__(256, 2) void proj_kernel(
    const float* __restrict__ F, const float* __restrict__ M,
    const float* __restrict__ Wm, const float* __restrict__ bias,
    const float* __restrict__ lnw, const float* __restrict__ lnb)
{
    extern __shared__ float psm[];
    float* const sWt = psm;                 // [c][d]
    float* const sX  = psm + CIN*DIM;       // [slice][8 c][512 vox]
    __shared__ float sB[DIM], sLW[DIM], sLB[DIM];

    const int tid  = threadIdx.x;
    const int lane = tid & 31;
    const int wrp  = tid >> 5;
    const float* __restrict__ src = blockIdx.y ? M : F;
    float* __restrict__ dst = blockIdx.y ? g_k : g_q;
    const int v0 = blockIdx.x * PVOX;

    // warp-local prefetch: warp w fills (and later consumes) voxels [64w,64w+64)
#pragma unroll
    for (int s = 0; s < NSL; s++) {
#pragma unroll
        for (int i = 0; i < 4; i++) {
            const int m  = lane + 32*i;
            const int c  = m >> 4;
            const int f0 = (m & 15) * 4;
            cp_async16(&sX[(s*CS2 + c)*PVOX + 64*wrp + f0],
                       src + (size_t)(s*CS2 + c)*NVOX + v0 + 64*wrp + f0);
        }
        CP_COMMIT();
    }

    for (int i = tid; i < DIM*CIN; i += 256) {
        const int d = i / CIN, c = i - d*CIN;
        sWt[c*DIM + d] = Wm[i];
    }
    if (tid < DIM) { sB[tid] = bias[tid]; sLW[tid] = lnw[tid]; sLB[tid] = lnb[tid]; }
    __syncthreads();

    const int g  = tid & 3;          // d-group: d in [12g, 12g+12)
    const int ql = (tid >> 2) & 7;   // lane quad within warp
    const int vb = 64*wrp + 2*ql;    // voxel base; voxels vb+16i+{0,1}

    ull acc[48];                     // [vox 8][d-pair 6]
#pragma unroll
    for (int j = 0; j < 6; j++) {
        ull b2;
        PACK_F32X2(b2, sB[12*g + 2*j], sB[12*g + 2*j + 1]);
#pragma unroll
        for (int i = 0; i < 8; i++) acc[i*6 + j] = b2;
    }

#pragma unroll
    for (int cs = 0; cs < NSL; cs++) {
        if (cs == 0)      { CP_WAIT(3); }
        else if (cs == 1) { CP_WAIT(2); }
        else if (cs == 2) { CP_WAIT(1); }
        else              { CP_WAIT(0); }
        __syncwarp();

        const float* __restrict__ xb = sX + cs*CS2*PVOX;
#pragma unroll
        for (int cl = 0; cl < CS2; cl++) {
            const int c = cs*CS2 + cl;
            const float* __restrict__ xrow = xb + cl*PVOX + vb;
            ull xx[8];
#pragma unroll
            for (int i = 0; i < 4; i++) {
                const float2 xs = *(const float2*)(xrow + 16*i);   // LDS.64
                PACK_F32X2(xx[2*i  ], xs.x, xs.x);
                PACK_F32X2(xx[2*i+1], xs.y, xs.y);
            }
            const ulonglong2* __restrict__ wr = (const ulonglong2*)(sWt + c*DIM + 12*g);
            const ulonglong2 w0 = wr[0];
            const ulonglong2 w1 = wr[1];
            const ulonglong2 w2 = wr[2];
#pragma unroll
            for (int i = 0; i < 8; i++) {
                FMA_F32X2(acc[i*6 + 0], w0.x, xx[i], acc[i*6 + 0]);
                FMA_F32X2(acc[i*6 + 1], w0.y, xx[i], acc[i*6 + 1]);
                FMA_F32X2(acc[i*6 + 2], w1.x, xx[i], acc[i*6 + 2]);
                FMA_F32X2(acc[i*6 + 3], w1.y, xx[i], acc[i*6 + 3]);
                FMA_F32X2(acc[i*6 + 4], w2.x, xx[i], acc[i*6 + 4]);
                FMA_F32X2(acc[i*6 + 5], w2.y, xx[i], acc[i*6 + 5]);
            }
        }
    }

    float mu[8], rs[8];
#pragma unroll
    for (int i = 0; i < 8; i++) {
        float sum = 0.f, sq = 0.f;
#pragma unroll
        for (int j = 0; j < 6; j++) {
            float a, b;
            UNPACK_F32X2(a, b, acc[i*6 + j]);
            sum += a + b;
            sq = fmaf(a, a, sq);
            sq = fmaf(b, b, sq);
        }
        sum += __shfl_xor_sync(0xffffffffu, sum, 1);
        sq  += __shfl_xor_sync(0xffffffffu, sq, 1);
        sum += __shfl_xor_sync(0xffffffffu, sum, 2);
        sq  += __shfl_xor_sync(0xffffffffu, sq, 2);
        mu[i] = sum * (1.f/48.f);
        rs[i] = rsqrtf(sq * (1.f/48.f) - mu[i]*mu[i] + LN_EPS);
    }

    const int vbase = v0 + vb;
#pragma unroll
    for (int j = 0; j < 6; j++) {
        const int d0 = 12*g + 2*j;
        const int p  = 6*g + j;
        const float w0l = sLW[d0], w1l = sLW[d0+1];
        const float b0l = sLB[d0], b1l = sLB[d0+1];
#pragma unroll
        for (int i = 0; i < 4; i++) {
            float a0, b0v, a1, b1v;
            UNPACK_F32X2(a0, b0v, acc[(2*i  )*6 + j]);
            UNPACK_F32X2(a1, b1v, acc[(2*i+1)*6 + j]);
            __stcs((float4*)(dst + ((size_t)p*NVOX + vbase + 16*i)*2),
                   make_float4(
                       (a0  - mu[2*i  ]) * rs[2*i  ] * w0l + b0l,
                       (b0v - mu[2*i  ]) * rs[2*i  ] * w1l + b1l,
                       (a1  - mu[2*i+1]) * rs[2*i+1] * w0l + b0l,
                       (b1v - mu[2*i+1]) * rs[2*i+1] * w1l + b1l));
        }
    }
}

// ==== kernel B: 27-neighbor attention, 2-t blocking, 8w x 40t, occ 7 ========
#define LSTR2  42                 // ull slots per line: 40 t + 2 halo (real data)
#define NLINE2 30                 // 3 (h) x 10 (w)
#define D2ST   (NLINE2*LSTR2)     // 1260 ull per d-pair
#define SMEM_ATTN (3*D2ST*8)      // 30240 B

__global__ __launch_bounds__(160, 7) void attn_kernel(
    const float* __restrict__ rpb, float* __restrict__ out)
{
    extern __shared__ ull ks[];        // [3 d-pairs][30 lines][42 slots]
    __shared__ ull s_rpb2[27];
    __shared__ float red[5];

    const int tid  = threadIdx.x;
    const int bx   = blockIdx.x;        // 0..1599 (80 h x 10 wq x 2 th)
    const int head = blockIdx.y;        // 0..7
    const int h    = bx / 20;
    const int rem  = bx - h*20;
    const int w0   = (rem >> 1) * 8;    // 8-wide w strip
    const int t0   = (rem & 1) * 40;    // t half
    const int pb   = head * 3;          // d-pair base

    if (tid < 27) {
        const float r = rpb[head*27 + tid];
        ull r2; PACK_F32X2(r2, r, r);
        s_rpb2[tid] = r2;
    }

    // fill (halo slots carry real neighbor data at interior t-splits)
    const ull* __restrict__ gk2 = (const ull*)g_k;
    for (int i = tid; i < NLINE2*LSTR2; i += 160) {
        const int line = i / LSTR2;
        const int tpr  = i - line*LSTR2;
        const int l10  = line / 10;
        const int lh   = h + l10 - 1;
        const int lw   = w0 + (line - l10*10) - 1;
        const int tg   = t0 - 1 + tpr;
        ull k0 = 0ull, k1 = 0ull, k2 = 0ull;
        if ((unsigned)lh < (unsigned)HWT && (unsigned)lw < (unsigned)HWT &&
            (unsigned)tg < (unsigned)HWT) {
            const size_t gb = (size_t)pb*NVOX + (size_t)((lh*HWT + lw)*HWT + tg);
            k0 = gk2[gb];
            k1 = gk2[gb + NVOX];
            k2 = gk2[gb + 2*(size_t)NVOX];
        }
        ks[i]           = k0;
        ks[D2ST + i]    = k1;
        ks[2*D2ST + i]  = k2;
    }

    // q for this thread's two voxels (t, t+1): three LDG.128
    const int u  = tid % 20;            // t-pair within 40-t half
    const int wl = tid / 20;            // 0..7
    const int tl = 2*u;
    const int v  = (h*HWT + (w0 + wl))*HWT + t0 + tl;
    const ull* __restrict__ gq = (const ull*)g_q;
    const ulonglong2 Q0 = *(const ulonglong2*)(gq + (size_t)(pb + 0)*NVOX + v);
    const ulonglong2 Q1 = *(const ulonglong2*)(gq + (size_t)(pb + 1)*NVOX + v);
    const ulonglong2 Q2 = *(const ulonglong2*)(gq + (size_t)(pb + 2)*NVOX + v);
    __syncthreads();

    const ull* __restrict__ kb = ks;

    ull c_m1;
    PACK_F32X2(c_m1, -1.f, -1.f);

    // packed state across voxel pair: lo = voxel t, hi = voxel t+1
    ull s2 = 0ull, mx2 = 0ull, my2 = 0ull, mz2 = 0ull, sc2 = 0ull;

#pragma unroll
    for (int o9 = 0; o9 < 9; o9++) {
        const int oi = o9 / 3, oj = o9 % 3;
        const int base = (oi*10 + wl + oj)*LSTR2 + tl;
        ull la0 = 0ull, la1 = 0ull, la2 = 0ull;
        ull lb0 = 0ull, lb1 = 0ull, lb2 = 0ull;
#pragma unroll
        for (int d2 = 0; d2 < 3; d2++) {
            const ulonglong2 A = *(const ulonglong2*)(kb + d2*D2ST + base);
            const ulonglong2 B = *(const ulonglong2*)(kb + d2*D2ST + base + 2);
            const ull qa = (d2 == 0) ? Q0.x : ((d2 == 1) ? Q1.x : Q2.x);
            const ull qb = (d2 == 0) ? Q0.y : ((d2 == 1) ? Q1.y : Q2.y);
            FMA_F32X2(la0, qa, A.x, la0);
            FMA_F32X2(la1, qa, A.y, la1);
            FMA_F32X2(la2, qa, B.x, la2);
            FMA_F32X2(lb0, qb, A.y, lb0);
            FMA_F32X2(lb1, qb, B.x, lb1);
            FMA_F32X2(lb2, qb, B.y, lb2);
        }
#pragma unroll
        for (int ol = 0; ol < 3; ol++) {
            const ull lva = (ol == 0) ? la0 : ((ol == 1) ? la1 : la2);
            const ull lvb = (ol == 0) ? lb0 : ((ol == 1) ? lb1 : lb2);
            float x1, x2, y1, y2;
            UNPACK_F32X2(x1, x2, lva);
            UNPACK_F32X2(y1, y2, lvb);
            ull a2;
            PACK_F32X2(a2, x1 + x2, y1 + y2);
            ADD_F32X2(a2, a2, s_rpb2[o9*3 + ol]);
            if (o9 == 4 && ol == 2) sc2 = a2;   // score channel o=14
            float aa, ab;
            UNPACK_F32X2(aa, ab, a2);
            ull e2;
            PACK_F32X2(e2, __expf(aa), __expf(ab)); // max-free: |a| O(10)
            ADD_F32X2(s2, s2, e2);
            if (oi == 0)      FMA_F32X2(mx2, e2, c_m1, mx2);
            else if (oi == 2) ADD_F32X2(mx2, mx2, e2);
            if (oj == 0)      FMA_F32X2(my2, e2, c_m1, my2);
            else if (oj == 2) ADD_F32X2(my2, my2, e2);
            if (ol == 0)      FMA_F32X2(mz2, e2, c_m1, mz2);
            else if (ol == 2) ADD_F32X2(mz2, mz2, e2);
        }
    }

    float sa, sb_;
    UNPACK_F32X2(sa, sb_, s2);
    const float ia = __fdividef(1.f, sa);
    const float ib = __fdividef(1.f, sb_);
    {
        float m0, m1;
        UNPACK_F32X2(m0, m1, mx2);
        *(float2*)&out[(size_t)(head*3 + 0)*NVOX + v] = make_float2(m0*ia, m1*ib);
        UNPACK_F32X2(m0, m1, my2);
        *(float2*)&out[(size_t)(head*3 + 1)*NVOX + v] = make_float2(m0*ia, m1*ib);
        UNPACK_F32X2(m0, m1, mz2);
        *(float2*)&out[(size_t)(head*3 + 2)*NVOX + v] = make_float2(m0*ia, m1*ib);
    }

    // deterministic block reduction of score channel
    float sc;
    {
        float a, b;
        UNPACK_F32X2(a, b, sc2);
        sc = a + b;
    }
#pragma unroll
    for (int off = 16; off; off >>= 1) sc += __shfl_down_sync(0xffffffffu, sc, off);
    if ((tid & 31) == 0) red[tid >> 5] = sc;
    __syncthreads();
    if (tid < 32) {
        float v2 = (tid < 5) ? red[tid] : 0.f;
#pragma unroll
        for (int off = 16; off; off >>= 1) v2 += __shfl_down_sync(0xffffffffu, v2, off);
        if (tid == 0) g_partial[head*1600 + bx] = v2;
    }
}

// ---------------- kernel C: deterministic final score reduction -------------
__global__ __launch_bounds__(256) void score_kernel(float* __restrict__ out)
{
    __shared__ double sd[256];
    const int tid = threadIdx.x;
    double a = 0.0;
    for (int i = tid; i < 1600*NHEADS; i += 256) a += (double)g_partial[i];
    sd[tid] = a;
    __syncthreads();
    for (int s = 128; s > 0; s >>= 1) {
        if (tid < s) sd[tid] += sd[tid + s];
        __syncthreads();
    }
    if (tid == 0) out[NMOT] = (float)(sd[0] * (1.0 / 4096000.0));
}

// ---------------- launch -----------------------------------------------------
extern "C" void kernel_launch(void* const* d_in, const int* in_sizes, int n_in,
                              void* d_out, int out_size)
{
    const float* F   = (const float*)d_in[0];
    const float* M   = (const float*)d_in[1];
    const float* Wm  = (const float*)d_in[2];
    const float* b   = (const float*)d_in[3];
    const float* lnw = (const float*)d_in[4];
    const float* lnb = (const float*)d_in[5];
    const float* rpb = (const float*)d_in[6];
    float* out = (float*)d_out;

    cudaFuncSetAttribute(proj_kernel, cudaFuncAttributeMaxDynamicSharedMemorySize, PROJ_SMEM);
    cudaFuncSetAttribute(attn_kernel, cudaFuncAttributeMaxDynamicSharedMemorySize, SMEM_ATTN);

    proj_kernel<<<dim3(NVOX/PVOX, 2, 1), 256, PROJ_SMEM>>>(F, M, Wm, b, lnw, lnb);
    attn_kernel<<<dim3(1600, NHEADS, 1), 160, SMEM_ATTN>>>(rpb, out);
    if (out_size > NMOT) score_kernel<<<1, 256>>>(out);
}

// round 16
// speedup vs baseline: 1.0201x; 1.0201x over previous
#include <cuda_runtime.h>

// ---------------- problem constants ----------------
#define HWT    80
#define NVOX   (HWT*HWT*HWT)      // 512000
#define CIN    32
#define DIM    48
#define NHEADS 8
#define HD     6
#define NMOT   (NHEADS*3*NVOX)
#define LN_EPS 1e-5f

typedef unsigned long long ull;

// ---------------- packed fp32x2 helpers (sm_103a) ----------------
#define FMA_F32X2(d, a, b, c) \
    asm("fma.rn.f32x2 %0, %1, %2, %3;" : "=l"(d) : "l"(a), "l"(b), "l"(c))
#define ADD_F32X2(d, a, b) \
    asm("add.rn.f32x2 %0, %1, %2;" : "=l"(d) : "l"(a), "l"(b))
#define PACK_F32X2(out, lo, hi) \
    asm("mov.b64 %0, {%1, %2};" : "=l"(out) : "f"(lo), "f"(hi))
#define UNPACK_F32X2(lo, hi, in) \
    asm("mov.b64 {%0, %1}, %2;" : "=f"(lo), "=f"(hi) : "l"(in))

// ---------------- cp.async helpers ----------------
__device__ __forceinline__ void cp_async16(void* s, const void* g) {
    unsigned saddr = (unsigned)__cvta_generic_to_shared(s);
    asm volatile("cp.async.cg.shared.global [%0], [%1], 16;\n" :: "r"(saddr), "l"(g));
}
#define CP_COMMIT()  asm volatile("cp.async.commit_group;\n" ::: "memory")
#define CP_WAIT(n)   asm volatile("cp.async.wait_group %0;\n" :: "n"(n) : "memory")

// ---------------- scratch (static device globals) ----------------
// q/k pair-interleaved: [24 d-pairs][NVOX][2]
__device__ float g_q[(size_t)DIM*NVOX];
__device__ float g_k[(size_t)DIM*NVOX];
__device__ float g_partial[800*NHEADS];

// ===== kernel A: Linear(32->48)+LN, 4 vox x 12 d / thread, occ 3 ============
#define CS2   8
#define NSL   4
#define PVOX  256
#define PROJ_SMEM ((CIN*DIM + NSL*CS2*PVOX)*4)   // 38912 B

__global__ __launch_bounds__(256, 3) void proj_kernel(
    const float* __restrict__ F, const float* __restrict__ M,
    const float* __restrict__ Wm, const float* __restrict__ bias,
    const float* __restrict__ lnw, const float* __restrict__ lnb)
{
    extern __shared__ float psm[];
    float* const sWt = psm;                 // [c][d]
    float* const sX  = psm + CIN*DIM;       // [slice][8 c][256 vox]
    __shared__ float sB[DIM], sLW[DIM], sLB[DIM];

    const int tid  = threadIdx.x;
    const int lane = tid & 31;
    const int wrp  = tid >> 5;
    const float* __restrict__ src = blockIdx.y ? M : F;
    float* __restrict__ dst = blockIdx.y ? g_k : g_q;
    const int v0 = blockIdx.x * PVOX;

    // warp-local prefetch: warp w fills (and consumes) voxels [32w, 32w+32)
    // per slice: 8 c x 32 vox x 4 B = 1 KB = 64 x 16B chunks, 2 per lane
#pragma unroll
    for (int s = 0; s < NSL; s++) {
#pragma unroll
        for (int i = 0; i < 2; i++) {
            const int m  = lane + 32*i;       // 0..63
            const int c  = m >> 3;            // 0..7
            const int f0 = (m & 7) * 4;       // float offset in 32-vox segment
            cp_async16(&sX[(s*CS2 + c)*PVOX + 32*wrp + f0],
                       src + (size_t)(s*CS2 + c)*NVOX + v0 + 32*wrp + f0);
        }
        CP_COMMIT();
    }

    for (int i = tid; i < DIM*CIN; i += 256) {
        const int d = i / CIN, c = i - d*CIN;
        sWt[c*DIM + d] = Wm[i];
    }
    if (tid < DIM) { sB[tid] = bias[tid]; sLW[tid] = lnw[tid]; sLB[tid] = lnb[tid]; }
    __syncthreads();

    const int g  = tid & 3;          // d-group: d in [12g, 12g+12)
    const int ql = (tid >> 2) & 7;   // pair-slot within warp
    const int vb = 32*wrp + 2*ql;    // voxel base; voxels vb,vb+1, vb+16,vb+17

    ull acc[24];                     // [vox 4][d-pair 6]
#pragma unroll
    for (int j = 0; j < 6; j++) {
        ull b2;
        PACK_F32X2(b2, sB[12*g + 2*j], sB[12*g + 2*j + 1]);
#pragma unroll
        for (int i = 0; i < 4; i++) acc[i*6 + j] = b2;
    }

#pragma unroll
    for (int cs = 0; cs < NSL; cs++) {
        if (cs == 0)      { CP_WAIT(3); }
        else if (cs == 1) { CP_WAIT(2); }
        else if (cs == 2) { CP_WAIT(1); }
        else              { CP_WAIT(0); }
        __syncwarp();

        const float* __restrict__ xb = sX + cs*CS2*PVOX;
#pragma unroll
        for (int cl = 0; cl < CS2; cl++) {
            const int c = cs*CS2 + cl;
            const float* __restrict__ xrow = xb + cl*PVOX + vb;
            const float2 xs0 = *(const float2*)(xrow);        // LDS.64 broadcast
            const float2 xs1 = *(const float2*)(xrow + 16);
            ull xx[4];
            PACK_F32X2(xx[0], xs0.x, xs0.x);
            PACK_F32X2(xx[1], xs0.y, xs0.y);
            PACK_F32X2(xx[2], xs1.x, xs1.x);
            PACK_F32X2(xx[3], xs1.y, xs1.y);
            const ulonglong2* __restrict__ wr = (const ulonglong2*)(sWt + c*DIM + 12*g);
            const ulonglong2 w0 = wr[0];
            const ulonglong2 w1 = wr[1];
            const ulonglong2 w2 = wr[2];
#pragma unroll
            for (int i = 0; i < 4; i++) {
                FMA_F32X2(acc[i*6 + 0], w0.x, xx[i], acc[i*6 + 0]);
                FMA_F32X2(acc[i*6 + 1], w0.y, xx[i], acc[i*6 + 1]);
                FMA_F32X2(acc[i*6 + 2], w1.x, xx[i], acc[i*6 + 2]);
                FMA_F32X2(acc[i*6 + 3], w1.y, xx[i], acc[i*6 + 3]);
                FMA_F32X2(acc[i*6 + 4], w2.x, xx[i], acc[i*6 + 4]);
                FMA_F32X2(acc[i*6 + 5], w2.y, xx[i], acc[i*6 + 5]);
            }
        }
    }

    // LN stats: partial over 12 d, combine across 4 d-group lanes via shfl
    float mu[4], rs[4];
#pragma unroll
    for (int i = 0; i < 4; i++) {
        float sum = 0.f, sq = 0.f;
#pragma unroll
        for (int j = 0; j < 6; j++) {
            float a, b;
            UNPACK_F32X2(a, b, acc[i*6 + j]);
            sum += a + b;
            sq = fmaf(a, a, sq);
            sq = fmaf(b, b, sq);
        }
        sum += __shfl_xor_sync(0xffffffffu, sum, 1);
        sq  += __shfl_xor_sync(0xffffffffu, sq, 1);
        sum += __shfl_xor_sync(0xffffffffu, sum, 2);
        sq  += __shfl_xor_sync(0xffffffffu, sq, 2);
        mu[i] = sum * (1.f/48.f);
        rs[i] = rsqrtf(sq * (1.f/48.f) - mu[i]*mu[i] + LN_EPS);
    }

    // pair-interleaved writeout: voxel pairs (vb,vb+1) and (vb+16,vb+17)
    const int vbase = v0 + vb;
#pragma unroll
    for (int j = 0; j < 6; j++) {
        const int d0 = 12*g + 2*j;
        const int p  = 6*g + j;
        const float w0l = sLW[d0], w1l = sLW[d0+1];
        const float b0l = sLB[d0], b1l = sLB[d0+1];
#pragma unroll
        for (int i = 0; i < 2; i++) {
            float a0, b0v, a1, b1v;
            UNPACK_F32X2(a0, b0v, acc[(2*i  )*6 + j]);
            UNPACK_F32X2(a1, b1v, acc[(2*i+1)*6 + j]);
            __stcs((float4*)(dst + ((size_t)p*NVOX + vbase + 16*i)*2),
                   make_float4(
                       (a0  - mu[2*i  ]) * rs[2*i  ] * w0l + b0l,
                       (b0v - mu[2*i  ]) * rs[2*i  ] * w1l + b1l,
                       (a1  - mu[2*i+1]) * rs[2*i+1] * w0l + b0l,
                       (b1v - mu[2*i+1]) * rs[2*i+1] * w1l + b1l));
        }
    }
}

// ======== kernel B: 27-neighbor attention, 2-t blocking, packed epilogue ====
// (R14 proven configuration: 320 threads, 8w x 80t, occ 3)
#define LSTR   82            // float2 units per line (80 + 2 halo)
#define D2STRn (30*LSTR)     // 2460 float2 units per d-pair (30 lines)
#define SMEM_ATTN (3*D2STRn*8)   // 59040 B

__global__ __launch_bounds__(320, 3) void attn_kernel(
    const float* __restrict__ rpb, float* __restrict__ out)
{
    extern __shared__ float2 ks[];     // [3 d-pairs][30 lines][82 t]
    __shared__ ull s_rpb2[27];
    __shared__ float red[10];

    const int tid  = threadIdx.x;
    const int bx   = blockIdx.x;        // 0..799
    const int head = blockIdx.y;        // 0..7
    const int h    = bx / 10;
    const int w0   = (bx - h*10) * 8;   // 8-wide w strip
    const int pb   = head * 3;          // d-pair base

    if (tid < 27) {
        const float r = rpb[head*27 + tid];
        ull r2; PACK_F32X2(r2, r, r);
        s_rpb2[tid] = r2;
    }

    // zero t-halo (t'=0, t'=81): 3*30*2 = 180 slots
    if (tid < 180) {
        const int d2 = tid / 60, r = tid - d2*60;
        const int line = r >> 1, e = r & 1;
        ks[d2*D2STRn + line*LSTR + (e ? 81 : 0)] = make_float2(0.f, 0.f);
    }

    // coalesced fill: 30 lines x 80 t, 3 d-pairs per index
    const float2* __restrict__ gk2 = (const float2*)g_k;
    for (int i = tid; i < 30*80; i += 320) {
        const int line = i / 80;
        const int tt   = i - line*80;
        const int l10  = line / 10;
        const int lh   = h + l10 - 1;
        const int lw   = w0 + (line - l10*10) - 1;
        const int sb   = line*LSTR + tt + 1;
        float2 k0 = make_float2(0.f,0.f), k1 = k0, k2 = k0;
        if (lh >= 0 && lh < HWT && lw >= 0 && lw < HWT) {
            const size_t gb = (size_t)pb*NVOX + (size_t)((lh*HWT + lw)*HWT + tt);
            k0 = gk2[gb];
            k1 = gk2[gb + NVOX];
            k2 = gk2[gb + 2*(size_t)NVOX];
        }
        ks[sb]            = k0;
        ks[D2STRn + sb]   = k1;
        ks[2*D2STRn + sb] = k2;
    }

    // q for this thread's two voxels (t, t+1): three LDG.128
    const int u  = tid % 40;
    const int wl = tid / 40;            // 0..7
    const int t  = 2*u;
    const int v  = (h*HWT + (w0 + wl))*HWT + t;
    const ull* __restrict__ gq = (const ull*)g_q;
    const ulonglong2 Q0 = *(const ulonglong2*)(gq + (size_t)(pb + 0)*NVOX + v);
    const ulonglong2 Q1 = *(const ulonglong2*)(gq + (size_t)(pb + 1)*NVOX + v);
    const ulonglong2 Q2 = *(const ulonglong2*)(gq + (size_t)(pb + 2)*NVOX + v);
    __syncthreads();

    const ull* __restrict__ kb = (const ull*)ks;

    ull c_m1;
    PACK_F32X2(c_m1, -1.f, -1.f);

    // packed state across voxel pair: lo = voxel t, hi = voxel t+1
    ull s2 = 0ull, mx2 = 0ull, my2 = 0ull, mz2 = 0ull, sc2 = 0ull;

#pragma unroll
    for (int o9 = 0; o9 < 9; o9++) {
        const int oi = o9 / 3, oj = o9 % 3;
        const int base = (oi*10 + wl + oj)*LSTR + t;
        ull la0 = 0ull, la1 = 0ull, la2 = 0ull;
        ull lb0 = 0ull, lb1 = 0ull, lb2 = 0ull;
#pragma unroll
        for (int d2 = 0; d2 < 3; d2++) {
            const ulonglong2 A = *(const ulonglong2*)(kb + d2*D2STRn + base);
            const ulonglong2 B = *(const ulonglong2*)(kb + d2*D2STRn + base + 2);
            const ull qa = (d2 == 0) ? Q0.x : ((d2 == 1) ? Q1.x : Q2.x);
            const ull qb = (d2 == 0) ? Q0.y : ((d2 == 1) ? Q1.y : Q2.y);
            FMA_F32X2(la0, qa, A.x, la0);
            FMA_F32X2(la1, qa, A.y, la1);
            FMA_F32X2(la2, qa, B.x, la2);
            FMA_F32X2(lb0, qb, A.y, lb0);
            FMA_F32X2(lb1, qb, B.x, lb1);
            FMA_F32X2(lb2, qb, B.y, lb2);
        }
#pragma unroll
        for (int ol = 0; ol < 3; ol++) {
            const ull lva = (ol == 0) ? la0 : ((ol == 1) ? la1 : la2);
            const ull lvb = (ol == 0) ? lb0 : ((ol == 1) ? lb1 : lb2);
            float x1, x2, y1, y2;
            UNPACK_F32X2(x1, x2, lva);
            UNPACK_F32X2(y1, y2, lvb);
            ull a2;
            PACK_F32X2(a2, x1 + x2, y1 + y2);
            ADD_F32X2(a2, a2, s_rpb2[o9*3 + ol]);
            if (o9 == 4 && ol == 2) sc2 = a2;   // score channel o=14
            float aa, ab;
            UNPACK_F32X2(aa, ab, a2);
            ull e2;
            PACK_F32X2(e2, __expf(aa), __expf(ab)); // max-free: |a| O(10)
            ADD_F32X2(s2, s2, e2);
            if (oi == 0)      FMA_F32X2(mx2, e2, c_m1, mx2);
            else if (oi == 2) ADD_F32X2(mx2, mx2, e2);
            if (oj == 0)      FMA_F32X2(my2, e2, c_m1, my2);
            else if (oj == 2) ADD_F32X2(my2, my2, e2);
            if (ol == 0)      FMA_F32X2(mz2, e2, c_m1, mz2);
            else if (ol == 2) ADD_F32X2(mz2, mz2, e2);
        }
    }

    float sa, sb_;
    UNPACK_F32X2(sa, sb_, s2);
    const float ia = __fdividef(1.f, sa);
    const float ib = __fdividef(1.f, sb_);
    {
        float m0, m1;
        UNPACK_F32X2(m0, m1, mx2);
        *(float2*)&out[(size_t)(head*3 + 0)*NVOX + v] = make_float2(m0*ia, m1*ib);
        UNPACK_F32X2(m0, m1, my2);
        *(float2*)&out[(size_t)(head*3 + 1)*NVOX + v] = make_float2(m0*ia, m1*ib);
        UNPACK_F32X2(m0, m1, mz2);
        *(float2*)&out[(size_t)(head*3 + 2)*NVOX + v] = make_float2(m0*ia, m1*ib);
    }

    // deterministic block reduction of score channel
    float sc;
    {
        float a, b;
        UNPACK_F32X2(a, b, sc2);
        sc = a + b;
    }
#pragma unroll
    for (int off = 16; off; off >>= 1) sc += __shfl_down_sync(0xffffffffu, sc, off);
    if ((tid & 31) == 0) red[tid >> 5] = sc;
    __syncthreads();
    if (tid < 32) {
        float v2 = (tid < 10) ? red[tid] : 0.f;
#pragma unroll
        for (int off = 16; off; off >>= 1) v2 += __shfl_down_sync(0xffffffffu, v2, off);
        if (tid == 0) g_partial[head*800 + bx] = v2;
    }
}

// ---------------- kernel C: deterministic final score reduction -------------
__global__ __launch_bounds__(256) void score_kernel(float* __restrict__ out)
{
    __shared__ double sd[256];
    const int tid = threadIdx.x;
    double a = 0.0;
    for (int i = tid; i < 800*NHEADS; i += 256) a += (double)g_partial[i];
    sd[tid] = a;
    __syncthreads();
    for (int s = 128; s > 0; s >>= 1) {
        if (tid < s) sd[tid] += sd[tid + s];
        __syncthreads();
    }
    if (tid == 0) out[NMOT] = (float)(sd[0] * (1.0 / 4096000.0));
}

// ---------------- launch -----------------------------------------------------
extern "C" void kernel_launch(void* const* d_in, const int* in_sizes, int n_in,
                              void* d_out, int out_size)
{
    const float* F   = (const float*)d_in[0];
    const float* M   = (const float*)d_in[1];
    const float* Wm  = (const float*)d_in[2];
    const float* b   = (const float*)d_in[3];
    const float* lnw = (const float*)d_in[4];
    const float* lnb = (const float*)d_in[5];
    const float* rpb = (const float*)d_in[6];
    float* out = (float*)d_out;

    cudaFuncSetAttribute(proj_kernel, cudaFuncAttributeMaxDynamicSharedMemorySize, PROJ_SMEM);
    cudaFuncSetAttribute(attn_kernel, cudaFuncAttributeMaxDynamicSharedMemorySize, SMEM_ATTN);

    proj_kernel<<<dim3(NVOX/PVOX, 2, 1), 256, PROJ_SMEM>>>(F, M, Wm, b, lnw, lnb);
    attn_kernel<<<dim3(800, NHEADS, 1), 320, SMEM_ATTN>>>(rpb, out);
    if (out_size > NMOT) score_kernel<<<1, 256>>>(out);
}

// round 17
// speedup vs baseline: 1.1731x; 1.1500x over previous
#include <cuda_runtime.h>

// ---------------- problem constants ----------------
#define HWT    80
#define NVOX   (HWT*HWT*HWT)      // 512000
#define CIN    32
#define DIM    48
#define NHEADS 8
#define HD     6
#define NMOT   (NHEADS*3*NVOX)
#define LN_EPS 1e-5f

typedef unsigned long long ull;

// ---------------- packed fp32x2 helpers (sm_103a) ----------------
#define FMA_F32X2(d, a, b, c) \
    asm("fma.rn.f32x2 %0, %1, %2, %3;" : "=l"(d) : "l"(a), "l"(b), "l"(c))
#define ADD_F32X2(d, a, b) \
    asm("add.rn.f32x2 %0, %1, %2;" : "=l"(d) : "l"(a), "l"(b))
#define PACK_F32X2(out, lo, hi) \
    asm("mov.b64 %0, {%1, %2};" : "=l"(out) : "f"(lo), "f"(hi))
#define UNPACK_F32X2(lo, hi, in) \
    asm("mov.b64 {%0, %1}, %2;" : "=f"(lo), "=f"(hi) : "l"(in))

// ---------------- cp.async helpers ----------------
__device__ __forceinline__ void cp_async16(void* s, const void* g) {
    unsigned saddr = (unsigned)__cvta_generic_to_shared(s);
    asm volatile("cp.async.cg.shared.global [%0], [%1], 16;\n" :: "r"(saddr), "l"(g));
}
__device__ __forceinline__ void cp_async8(void* s, const void* g) {
    unsigned saddr = (unsigned)__cvta_generic_to_shared(s);
    asm volatile("cp.async.ca.shared.global [%0], [%1], 8;\n" :: "r"(saddr), "l"(g));
}
#define CP_COMMIT()  asm volatile("cp.async.commit_group;\n" ::: "memory")
#define CP_WAIT(n)   asm volatile("cp.async.wait_group %0;\n" :: "n"(n) : "memory")

// ---------------- scratch (static device globals) ----------------
// q/k pair-interleaved: [24 d-pairs][NVOX][2]
__device__ float g_q[(size_t)DIM*NVOX];
__device__ float g_k[(size_t)DIM*NVOX];
__device__ float g_partial[800*NHEADS];

// ===== kernel A: Linear(32->48)+LN, 8 vox x 12 d / thread, cp.async =========
#define CS2   8
#define NSL   4
#define PVOX  512
#define PROJ_SMEM ((CIN*DIM + NSL*CS2*PVOX)*4)   // 71680 B

__global__ __launch_bounds__(256, 2) void proj_kernel(
    const float* __restrict__ F, const float* __restrict__ M,
    const float* __restrict__ Wm, const float* __restrict__ bias,
    const float* __restrict__ lnw, const float* __restrict__ lnb)
{
    extern __shared__ float psm[];
    float* const sWt = psm;                 // [c][d]
    float* const sX  = psm + CIN*DIM;       // [slice][8 c][512 vox]
    __shared__ float sB[DIM], sLW[DIM], sLB[DIM];

    const int tid  = threadIdx.x;
    const int lane = tid & 31;
    const int wrp  = tid >> 5;
    const float* __restrict__ src = blockIdx.y ? M : F;
    float* __restrict__ dst = blockIdx.y ? g_k : g_q;
    const int v0 = blockIdx.x * PVOX;

    // warp-local prefetch: warp w fills (and later consumes) voxels [64w,64w+64)
#pragma unroll
    for (int s = 0; s < NSL; s++) {
#pragma unroll
        for (int i = 0; i < 4; i++) {
            const int m  = lane + 32*i;
            const int c  = m >> 4;
            const int f0 = (m & 15) * 4;
            cp_async16(&sX[(s*CS2 + c)*PVOX + 64*wrp + f0],
                       src + (size_t)(s*CS2 + c)*NVOX + v0 + 64*wrp + f0);
        }
        CP_COMMIT();
    }

    for (int i = tid; i < DIM*CIN; i += 256) {
        const int d = i / CIN, c = i - d*CIN;
        sWt[c*DIM + d] = Wm[i];
    }
    if (tid < DIM) { sB[tid] = bias[tid]; sLW[tid] = lnw[tid]; sLB[tid] = lnb[tid]; }
    __syncthreads();

    const int g  = tid & 3;          // d-group: d in [12g, 12g+12)
    const int ql = (tid >> 2) & 7;   // lane quad within warp
    const int vb = 64*wrp + 2*ql;    // voxel base; voxels vb+16i+{0,1}

    ull acc[48];                     // [vox 8][d-pair 6]
#pragma unroll
    for (int j = 0; j < 6; j++) {
        ull b2;
        PACK_F32X2(b2, sB[12*g + 2*j], sB[12*g + 2*j + 1]);
#pragma unroll
        for (int i = 0; i < 8; i++) acc[i*6 + j] = b2;
    }

#pragma unroll
    for (int cs = 0; cs < NSL; cs++) {
        if (cs == 0)      { CP_WAIT(3); }
        else if (cs == 1) { CP_WAIT(2); }
        else if (cs == 2) { CP_WAIT(1); }
        else              { CP_WAIT(0); }
        __syncwarp();

        const float* __restrict__ xb = sX + cs*CS2*PVOX;
#pragma unroll
        for (int cl = 0; cl < CS2; cl++) {
            const int c = cs*CS2 + cl;
            const float* __restrict__ xrow = xb + cl*PVOX + vb;
            ull xx[8];
#pragma unroll
            for (int i = 0; i < 4; i++) {
                const float2 xs = *(const float2*)(xrow + 16*i);   // LDS.64
                PACK_F32X2(xx[2*i  ], xs.x, xs.x);
                PACK_F32X2(xx[2*i+1], xs.y, xs.y);
            }
            const ulonglong2* __restrict__ wr = (const ulonglong2*)(sWt + c*DIM + 12*g);
            const ulonglong2 w0 = wr[0];
            const ulonglong2 w1 = wr[1];
            const ulonglong2 w2 = wr[2];
#pragma unroll
            for (int i = 0; i < 8; i++) {
                FMA_F32X2(acc[i*6 + 0], w0.x, xx[i], acc[i*6 + 0]);
                FMA_F32X2(acc[i*6 + 1], w0.y, xx[i], acc[i*6 + 1]);
                FMA_F32X2(acc[i*6 + 2], w1.x, xx[i], acc[i*6 + 2]);
                FMA_F32X2(acc[i*6 + 3], w1.y, xx[i], acc[i*6 + 3]);
                FMA_F32X2(acc[i*6 + 4], w2.x, xx[i], acc[i*6 + 4]);
                FMA_F32X2(acc[i*6 + 5], w2.y, xx[i], acc[i*6 + 5]);
            }
        }
    }

    float mu[8], rs[8];
#pragma unroll
    for (int i = 0; i < 8; i++) {
        float sum = 0.f, sq = 0.f;
#pragma unroll
        for (int j = 0; j < 6; j++) {
            float a, b;
            UNPACK_F32X2(a, b, acc[i*6 + j]);
            sum += a + b;
            sq = fmaf(a, a, sq);
            sq = fmaf(b, b, sq);
        }
        sum += __shfl_xor_sync(0xffffffffu, sum, 1);
        sq  += __shfl_xor_sync(0xffffffffu, sq, 1);
        sum += __shfl_xor_sync(0xffffffffu, sum, 2);
        sq  += __shfl_xor_sync(0xffffffffu, sq, 2);
        mu[i] = sum * (1.f/48.f);
        rs[i] = rsqrtf(sq * (1.f/48.f) - mu[i]*mu[i] + LN_EPS);
    }

    const int vbase = v0 + vb;
#pragma unroll
    for (int j = 0; j < 6; j++) {
        const int d0 = 12*g + 2*j;
        const int p  = 6*g + j;
        const float w0l = sLW[d0], w1l = sLW[d0+1];
        const float b0l = sLB[d0], b1l = sLB[d0+1];
#pragma unroll
        for (int i = 0; i < 4; i++) {
            float a0, b0v, a1, b1v;
            UNPACK_F32X2(a0, b0v, acc[(2*i  )*6 + j]);
            UNPACK_F32X2(a1, b1v, acc[(2*i+1)*6 + j]);
            __stcs((float4*)(dst + ((size_t)p*NVOX + vbase + 16*i)*2),
                   make_float4(
                       (a0  - mu[2*i  ]) * rs[2*i  ] * w0l + b0l,
                       (b0v - mu[2*i  ]) * rs[2*i  ] * w1l + b1l,
                       (a1  - mu[2*i+1]) * rs[2*i+1] * w0l + b0l,
                       (b1v - mu[2*i+1]) * rs[2*i+1] * w1l + b1l));
        }
    }
}

// ======== kernel B: 27-neighbor attention, 2-t blocking, cp.async fill ======
#define LSTR   82            // float2 units per line (80 + 2 halo)
#define D2STRn (30*LSTR)     // 2460 float2 units per d-pair (30 lines)
#define SMEM_ATTN (3*D2STRn*8)   // 59040 B

__global__ __launch_bounds__(320, 3) void attn_kernel(
    const float* __restrict__ rpb, float* __restrict__ out)
{
    extern __shared__ float2 ks[];     // [3 d-pairs][30 lines][82 t]
    __shared__ ull s_rpb2[27];
    __shared__ float red[10];

    const int tid  = threadIdx.x;
    const int bx   = blockIdx.x;        // 0..799
    const int head = blockIdx.y;        // 0..7
    const int h    = bx / 10;
    const int w0   = (bx - h*10) * 8;   // 8-wide w strip
    const int pb   = head * 3;          // d-pair base

    if (tid < 27) {
        const float r = rpb[head*27 + tid];
        ull r2; PACK_F32X2(r2, r, r);
        s_rpb2[tid] = r2;
    }

    // zero t-halo (t'=0, t'=81): 3*30*2 = 180 slots
    if (tid < 180) {
        const int d2 = tid / 60, r = tid - d2*60;
        const int line = r >> 1, e = r & 1;
        ks[d2*D2STRn + line*LSTR + (e ? 81 : 0)] = make_float2(0.f, 0.f);
    }

    // fill: 30 lines x 80 t, 3 d-pairs; in-bounds via cp.async (8B), OOB -> STS 0
    const float2* __restrict__ gk2 = (const float2*)g_k;
    for (int i = tid; i < 30*80; i += 320) {
        const int line = i / 80;
        const int tt   = i - line*80;
        const int l10  = line / 10;
        const int lh   = h + l10 - 1;
        const int lw   = w0 + (line - l10*10) - 1;
        const int sb   = line*LSTR + tt + 1;
        if (lh >= 0 && lh < HWT && lw >= 0 && lw < HWT) {
            const float2* gsrc = gk2 + (size_t)pb*NVOX + (size_t)((lh*HWT + lw)*HWT + tt);
            cp_async8(&ks[sb],             gsrc);
            cp_async8(&ks[D2STRn + sb],    gsrc + NVOX);
            cp_async8(&ks[2*D2STRn + sb],  gsrc + 2*(size_t)NVOX);
        } else {
            const float2 z = make_float2(0.f, 0.f);
            ks[sb]            = z;
            ks[D2STRn + sb]   = z;
            ks[2*D2STRn + sb] = z;
        }
    }
    CP_COMMIT();

    // q for this thread's two voxels (t, t+1): three LDG.128 (overlap the fill)
    const int u  = tid % 40;
    const int wl = tid / 40;            // 0..7
    const int t  = 2*u;
    const int v  = (h*HWT + (w0 + wl))*HWT + t;
    const ull* __restrict__ gq = (const ull*)g_q;
    const ulonglong2 Q0 = *(const ulonglong2*)(gq + (size_t)(pb + 0)*NVOX + v);
    const ulonglong2 Q1 = *(const ulonglong2*)(gq + (size_t)(pb + 1)*NVOX + v);
    const ulonglong2 Q2 = *(const ulonglong2*)(gq + (size_t)(pb + 2)*NVOX + v);
    CP_WAIT(0);
    __syncthreads();

    const ull* __restrict__ kb = (const ull*)ks;

    ull c_m1;
    PACK_F32X2(c_m1, -1.f, -1.f);

    // packed state across voxel pair: lo = voxel t, hi = voxel t+1
    ull s2 = 0ull, mx2 = 0ull, my2 = 0ull, mz2 = 0ull, sc2 = 0ull;

#pragma unroll
    for (int o9 = 0; o9 < 9; o9++) {
        const int oi = o9 / 3, oj = o9 % 3;
        const int base = (oi*10 + wl + oj)*LSTR + t;
        ull la0 = 0ull, la1 = 0ull, la2 = 0ull;
        ull lb0 = 0ull, lb1 = 0ull, lb2 = 0ull;
#pragma unroll
        for (int d2 = 0; d2 < 3; d2++) {
            const ulonglong2 A = *(const ulonglong2*)(kb + d2*D2STRn + base);
            const ulonglong2 B = *(const ulonglong2*)(kb + d2*D2STRn + base + 2);
            const ull qa = (d2 == 0) ? Q0.x : ((d2 == 1) ? Q1.x : Q2.x);
            const ull qb = (d2 == 0) ? Q0.y : ((d2 == 1) ? Q1.y : Q2.y);
            FMA_F32X2(la0, qa, A.x, la0);
            FMA_F32X2(la1, qa, A.y, la1);
            FMA_F32X2(la2, qa, B.x, la2);
            FMA_F32X2(lb0, qb, A.y, lb0);
            FMA_F32X2(lb1, qb, B.x, lb1);
            FMA_F32X2(lb2, qb, B.y, lb2);
        }
#pragma unroll
        for (int ol = 0; ol < 3; ol++) {
            const ull lva = (ol == 0) ? la0 : ((ol == 1) ? la1 : la2);
            const ull lvb = (ol == 0) ? lb0 : ((ol == 1) ? lb1 : lb2);
            float x1, x2, y1, y2;
            UNPACK_F32X2(x1, x2, lva);
            UNPACK_F32X2(y1, y2, lvb);
            ull a2;
            PACK_F32X2(a2, x1 + x2, y1 + y2);
            ADD_F32X2(a2, a2, s_rpb2[o9*3 + ol]);
            if (o9 == 4 && ol == 2) sc2 = a2;   // score channel o=14
            float aa, ab;
            UNPACK_F32X2(aa, ab, a2);
            ull e2;
            PACK_F32X2(e2, __expf(aa), __expf(ab)); // max-free: |a| O(10)
            ADD_F32X2(s2, s2, e2);
            if (oi == 0)      FMA_F32X2(mx2, e2, c_m1, mx2);
            else if (oi == 2) ADD_F32X2(mx2, mx2, e2);
            if (oj == 0)      FMA_F32X2(my2, e2, c_m1, my2);
            else if (oj == 2) ADD_F32X2(my2, my2, e2);
            if (ol == 0)      FMA_F32X2(mz2, e2, c_m1, mz2);
            else if (ol == 2) ADD_F32X2(mz2, mz2, e2);
        }
    }

    float sa, sb_;
    UNPACK_F32X2(sa, sb_, s2);
    const float ia = __fdividef(1.f, sa);
    const float ib = __fdividef(1.f, sb_);
    {
        float m0, m1;
        UNPACK_F32X2(m0, m1, mx2);
        *(float2*)&out[(size_t)(head*3 + 0)*NVOX + v] = make_float2(m0*ia, m1*ib);
        UNPACK_F32X2(m0, m1, my2);
        *(float2*)&out[(size_t)(head*3 + 1)*NVOX + v] = make_float2(m0*ia, m1*ib);
        UNPACK_F32X2(m0, m1, mz2);
        *(float2*)&out[(size_t)(head*3 + 2)*NVOX + v] = make_float2(m0*ia, m1*ib);
    }

    // deterministic block reduction of score channel
    float sc;
    {
        float a, b;
        UNPACK_F32X2(a, b, sc2);
        sc = a + b;
    }
#pragma unroll
    for (int off = 16; off; off >>= 1) sc += __shfl_down_sync(0xffffffffu, sc, off);
    if ((tid & 31) == 0) red[tid >> 5] = sc;
    __syncthreads();
    if (tid < 32) {
        float v2 = (tid < 10) ? red[tid] : 0.f;
#pragma unroll
        for (int off = 16; off; off >>= 1) v2 += __shfl_down_sync(0xffffffffu, v2, off);
        if (tid == 0) g_partial[head*800 + bx] = v2;
    }
}

// ---------------- kernel C: deterministic final score reduction -------------
__global__ __launch_bounds__(256) void score_kernel(float* __restrict__ out)
{
    __shared__ double sd[256];
    const int tid = threadIdx.x;
    double a = 0.0;
    for (int i = tid; i < 800*NHEADS; i += 256) a += (double)g_partial[i];
    sd[tid] = a;
    __syncthreads();
    for (int s = 128; s > 0; s >>= 1) {
        if (tid < s) sd[tid] += sd[tid + s];
        __syncthreads();
    }
    if (tid == 0) out[NMOT] = (float)(sd[0] * (1.0 / 4096000.0));
}

// ---------------- launch -----------------------------------------------------
extern "C" void kernel_launch(void* const* d_in, const int* in_sizes, int n_in,
                              void* d_out, int out_size)
{
    const float* F   = (const float*)d_in[0];
    const float* M   = (const float*)d_in[1];
    const float* Wm  = (const float*)d_in[2];
    const float* b   = (const float*)d_in[3];
    const float* lnw = (const float*)d_in[4];
    const float* lnb = (const float*)d_in[5];
    const float* rpb = (const float*)d_in[6];
    float* out = (float*)d_out;

    cudaFuncSetAttribute(proj_kernel, cudaFuncAttributeMaxDynamicSharedMemorySize, PROJ_SMEM);
    cudaFuncSetAttribute(attn_kernel, cudaFuncAttributeMaxDynamicSharedMemorySize, SMEM_ATTN);

    proj_kernel<<<dim3(NVOX/PVOX, 2, 1), 256, PROJ_SMEM>>>(F, M, Wm, b, lnw, lnb);
    attn_kernel<<<dim3(800, NHEADS, 1), 320, SMEM_ATTN>>>(rpb, out);
    if (out_size > NMOT) score_kernel<<<1, 256>>>(out);
}